// round 14
// baseline (speedup 1.0000x reference)
#include <cuda_runtime.h>
#include <cuda_fp16.h>
#include <cstdint>

#define NNODE 8192
#define INDIM 256
#define HID   128

__device__ __half g_Ht16[HID * NNODE];

// ---------------------------------------------------------------------------
// helpers
// ---------------------------------------------------------------------------
__device__ __forceinline__ void mbar_init(uint32_t a, uint32_t n) {
    asm volatile("mbarrier.init.shared.b64 [%0], %1;" :: "r"(a), "r"(n) : "memory");
}
__device__ __forceinline__ void mbar_arrive(uint32_t a) {
    asm volatile("mbarrier.arrive.release.cta.shared::cta.b64 _, [%0];" :: "r"(a) : "memory");
}
__device__ __forceinline__ void mbar_wait(uint32_t a, uint32_t parity) {
    asm volatile(
        "{\n\t.reg .pred P;\n\t"
        "WL_%=:\n\t"
        "mbarrier.try_wait.parity.acquire.cta.shared::cta.b64 P, [%0], %1, 0x989680;\n\t"
        "@P bra.uni WD_%=;\n\t"
        "bra.uni WL_%=;\n\t"
        "WD_%=:\n\t}"
        :: "r"(a), "r"(parity) : "memory");
}
__device__ __forceinline__ void cp_async16(uint32_t smem_dst, const void* gmem_src) {
    asm volatile("cp.async.cg.shared.global [%0], [%1], 16;" :: "r"(smem_dst), "l"(gmem_src));
}
__device__ __forceinline__ void ldsm_x4(uint32_t* r, uint32_t addr) {
    asm volatile("ldmatrix.sync.aligned.m8n8.x4.shared.b16 {%0,%1,%2,%3}, [%4];"
        : "=r"(r[0]), "=r"(r[1]), "=r"(r[2]), "=r"(r[3]) : "r"(addr));
}
__device__ __forceinline__ void mma16816(float* d, const uint32_t* a, const uint32_t* bfr) {
    asm volatile(
        "mma.sync.aligned.m16n8k16.row.col.f32.f16.f16.f32 "
        "{%0,%1,%2,%3}, {%4,%5,%6,%7}, {%8,%9}, {%0,%1,%2,%3};"
        : "+f"(d[0]), "+f"(d[1]), "+f"(d[2]), "+f"(d[3])
        : "r"(a[0]), "r"(a[1]), "r"(a[2]), "r"(a[3]), "r"(bfr[0]), "r"(bfr[1]));
}
__device__ __forceinline__ void red_add(float* p, float v) {
    asm volatile("red.global.add.f32 [%0], %1;" :: "l"(p), "f"(v) : "memory");
}

// ---------------------------------------------------------------------------
// Kernel 1 (tensor-core): Ht16 = fp16( W @ x^T + b )   + zeroes `out`
//   (unchanged from round-13 winner)
// ---------------------------------------------------------------------------
static constexpr int H_RS    = 528;
static constexpr int H_SW    = 0;
static constexpr int H_SX    = 128 * H_RS;
static constexpr int H_SB    = H_SX + 32 * H_RS;
static constexpr int H_SMEM  = H_SB + 512;
static constexpr int H_TRS   = 80;
#define W_SCALE 32.0f
#define W_INV   (1.0f / 32.0f)

__global__ void __launch_bounds__(256, 2) ht_kernel(const float* __restrict__ x,
                                                    const float* __restrict__ W,
                                                    const float* __restrict__ b,
                                                    float* __restrict__ out) {
    extern __shared__ char hsm[];
    const uint32_t sm = (uint32_t)__cvta_generic_to_shared(hsm);
    const int tid = threadIdx.x;
    const int wid = tid >> 5, lane = tid & 31;
    const int j0  = blockIdx.x * 32;

    // zero this CTA's 16 KB slice of out
    {
        float4* oz = reinterpret_cast<float4*>(out) + (size_t)blockIdx.x * 1024;
#pragma unroll
        for (int i = 0; i < 4; i++)
            oz[tid + i * 256] = make_float4(0.f, 0.f, 0.f, 0.f);
    }

    const float4* wg = reinterpret_cast<const float4*>(W);
#pragma unroll
    for (int i = 0; i < 32; i++) {
        int idx = tid + i * 256;
        int row = idx >> 6, c4 = idx & 63;
        float4 v = __ldg(wg + idx);
        __half2 h0 = __floats2half2_rn(v.x * W_SCALE, v.y * W_SCALE);
        __half2 h1 = __floats2half2_rn(v.z * W_SCALE, v.w * W_SCALE);
        asm volatile("st.shared.v2.b32 [%0], {%1,%2};" ::
            "r"(sm + H_SW + row * H_RS + c4 * 8),
            "r"(*(uint32_t*)&h0), "r"(*(uint32_t*)&h1) : "memory");
    }
    const float4* xg = reinterpret_cast<const float4*>(x + (size_t)j0 * INDIM);
#pragma unroll
    for (int i = 0; i < 8; i++) {
        int idx = tid + i * 256;
        int row = idx >> 6, c4 = idx & 63;
        float4 v = __ldg(xg + idx);
        __half2 h0 = __floats2half2_rn(v.x, v.y);
        __half2 h1 = __floats2half2_rn(v.z, v.w);
        asm volatile("st.shared.v2.b32 [%0], {%1,%2};" ::
            "r"(sm + H_SX + row * H_RS + c4 * 8),
            "r"(*(uint32_t*)&h0), "r"(*(uint32_t*)&h1) : "memory");
    }
    if (tid < 128)
        reinterpret_cast<float*>(hsm + H_SB)[tid] = b[tid];
    __syncthreads();

    const int wm = wid >> 1, wn = wid & 1;
    const int g = lane >> 2, q = lane & 3;
    const uint32_t a_lo = (uint32_t)((lane & 15) * H_RS + (lane >> 4) * 16);
    const uint32_t b_lo = (uint32_t)((lane & 7) * H_RS + ((lane >> 3) & 1) * 16
                                     + (lane >> 4) * (8 * H_RS));
    const uint32_t a_base = sm + H_SW + wm * (32 * H_RS) + a_lo;
    const uint32_t b_base = sm + H_SX + wn * (16 * H_RS) + b_lo;

    float acc[2][2][4];
#pragma unroll
    for (int mt = 0; mt < 2; mt++)
#pragma unroll
        for (int nt = 0; nt < 2; nt++)
#pragma unroll
            for (int i = 0; i < 4; i++) acc[mt][nt][i] = 0.f;

#pragma unroll
    for (int kc = 0; kc < 16; kc++) {
        const uint32_t kb = kc * 32;
        uint32_t af[2][4], bf[4];
        ldsm_x4(af[0], a_base + kb);
        ldsm_x4(af[1], a_base + 16 * H_RS + kb);
        ldsm_x4(bf, b_base + kb);
        mma16816(acc[0][0], af[0], bf);
        mma16816(acc[1][0], af[1], bf);
        mma16816(acc[0][1], af[0], bf + 2);
        mma16816(acc[1][1], af[1], bf + 2);
    }
    __syncthreads();

    const float* bs = reinterpret_cast<const float*>(hsm + H_SB);
#pragma unroll
    for (int mt = 0; mt < 2; mt++) {
        int c0 = wm * 32 + mt * 16 + g;
        float b0 = bs[c0], b1 = bs[c0 + 8];
#pragma unroll
        for (int nt = 0; nt < 2; nt++) {
            int j = wn * 16 + nt * 8 + 2 * q;
            __half2 h0 = __floats2half2_rn(fmaf(acc[mt][nt][0], W_INV, b0),
                                           fmaf(acc[mt][nt][1], W_INV, b0));
            __half2 h1 = __floats2half2_rn(fmaf(acc[mt][nt][2], W_INV, b1),
                                           fmaf(acc[mt][nt][3], W_INV, b1));
            asm volatile("st.shared.b32 [%0], %1;" ::
                "r"(sm + c0 * H_TRS + j * 2), "r"(*(uint32_t*)&h0) : "memory");
            asm volatile("st.shared.b32 [%0], %1;" ::
                "r"(sm + (c0 + 8) * H_TRS + j * 2), "r"(*(uint32_t*)&h1) : "memory");
        }
    }
    __syncthreads();

#pragma unroll
    for (int i = 0; i < 2; i++) {
        int idx = tid + i * 256;
        int row = idx >> 2, c16 = idx & 3;
        uint32_t r0, r1, r2, r3;
        asm volatile("ld.shared.v4.b32 {%0,%1,%2,%3}, [%4];"
            : "=r"(r0), "=r"(r1), "=r"(r2), "=r"(r3)
            : "r"(sm + row * H_TRS + c16 * 16));
        *reinterpret_cast<uint4*>(g_Ht16 + (size_t)row * NNODE + j0 + c16 * 8) =
            make_uint4(r0, r1, r2, r3);
    }
}

// ---------------------------------------------------------------------------
// Kernel 2: out += G @ H. Grid (128 mtiles, 4 kquarters) = 512 CTAs,
//   2 CTAs/SM => ~1.73 waves with work-stealing (fixes 256-CTA wave imbalance).
//   Per CTA: M=64, N=128, K=2048, KT=64, S=4. red.add epilogue (4 partials).
// ---------------------------------------------------------------------------
static constexpr int S      = 4;
static constexpr int KT     = 64;
static constexpr int KQ     = NNODE / 4;       // 2048
static constexpr int NS     = KQ / KT;         // 32
static constexpr int RSA    = 144;
static constexpr int RSB    = 144;
static constexpr int A_SM   = 64 * RSA;        // 9216
static constexpr int B_SM   = 128 * RSB;       // 18432
static constexpr int STAGE  = A_SM + B_SM;     // 27648
static constexpr int TILE0  = 1024;
static constexpr int SMEM_BYTES = TILE0 + S * STAGE;  // 111616
#define A_SCALE 1024.0f
#define O_SCALE (1.0f / 1024.0f)

__global__ void __launch_bounds__(512, 2) gemm_kernel(const float* __restrict__ G,
                                                      float* __restrict__ out) {
    extern __shared__ char smem[];
    const uint32_t sb     = (uint32_t)__cvta_generic_to_shared(smem);
    const uint32_t full0  = sb;
    const uint32_t empty0 = sb + 64;
    const uint32_t tiles  = sb + TILE0;

    const int tid = threadIdx.x;
    const int wid = tid >> 5, lane = tid & 31;
    const int m0  = blockIdx.x * 64;
    const int k0  = blockIdx.y * KQ;

    if (tid == 0) {
#pragma unroll
        for (int s = 0; s < S; s++) {
            mbar_init(full0 + s * 8, 8);
            mbar_init(empty0 + s * 8, 8);
        }
    }
    __syncthreads();

    if (wid < 8) {
        // ============ producers ============
        const int r0 = tid >> 4, c16 = tid & 15;
        const int br0 = tid >> 3, c8 = tid & 7;
        const float4* a_src = reinterpret_cast<const float4*>(
            G + (size_t)(m0 + r0) * NNODE + k0) + c16;
        const __half* b_src = g_Ht16 + (size_t)br0 * NNODE + k0 + c8 * 8;
        const uint32_t a_dst = (uint32_t)(r0 * RSA + c16 * 8);
        const uint32_t b_dst = (uint32_t)(A_SM + br0 * RSB + c8 * 16);

        float4 buf[2][4];
#pragma unroll
        for (int j = 0; j < 2; j++)
#pragma unroll
            for (int i = 0; i < 4; i++)
                buf[j][i] = __ldcs(a_src + (size_t)i * 4 * NNODE + j * 16);

        int aslot = 0;
        for (int s = 0; s < NS; s++) {
            const int slot = s & 3, lap = s >> 2;
            if (lap > 0) mbar_wait(empty0 + slot * 8, (lap - 1) & 1);
            const uint32_t st = tiles + slot * STAGE;
#pragma unroll
            for (int i = 0; i < 4; i++)
                cp_async16(st + b_dst + i * (32 * RSB), b_src + (size_t)i * 32 * NNODE + s * KT);
            asm volatile("cp.async.commit_group;" ::: "memory");
            const int ib = s & 1;
#pragma unroll
            for (int i = 0; i < 4; i++) {
                float4 v = buf[ib][i];
                __half2 h0 = __floats2half2_rn(v.x * A_SCALE, v.y * A_SCALE);
                __half2 h1 = __floats2half2_rn(v.z * A_SCALE, v.w * A_SCALE);
                asm volatile("st.shared.v2.b32 [%0], {%1,%2};" ::
                    "r"(st + a_dst + i * (16 * RSA)),
                    "r"(*(uint32_t*)&h0), "r"(*(uint32_t*)&h1) : "memory");
            }
            if (s + 2 < NS) {
#pragma unroll
                for (int i = 0; i < 4; i++)
                    buf[ib][i] = __ldcs(a_src + (size_t)i * 4 * NNODE + (s + 2) * 16);
            }
            if (s >= 2) {
                asm volatile("cp.async.wait_group 2;" ::: "memory");
                __syncwarp();
                if (lane == 0) mbar_arrive(full0 + aslot * 8);
                if (++aslot == S) aslot = 0;
            }
        }
        asm volatile("cp.async.wait_group 0;" ::: "memory");
        __syncwarp();
        if (lane == 0) {
            mbar_arrive(full0 + aslot * 8);
            int a2 = aslot + 1; if (a2 == S) a2 = 0;
            mbar_arrive(full0 + a2 * 8);
        }
    } else {
        // ============ consumers ============
        const int cw = wid - 8;
        const int wm = cw >> 2, wn = cw & 3;
        const uint32_t a_lo = (uint32_t)((lane & 15) * RSA + (lane >> 4) * 16);
        const uint32_t b_lo = (uint32_t)((lane & 7) * RSB + ((lane >> 3) & 1) * 16
                                         + (lane >> 4) * (8 * RSB));
        const uint32_t a_base = tiles + wm * (32 * RSA) + a_lo;
        const uint32_t b_base = tiles + A_SM + wn * (32 * RSB) + b_lo;

        float acc[2][4][4];
#pragma unroll
        for (int mt = 0; mt < 2; mt++)
#pragma unroll
            for (int nt = 0; nt < 4; nt++)
#pragma unroll
                for (int i = 0; i < 4; i++) acc[mt][nt][i] = 0.f;

        for (int s = 0; s < NS; s++) {
            const int slot = s & 3;
            mbar_wait(full0 + slot * 8, (s >> 2) & 1);
            const uint32_t soff = (uint32_t)(slot * STAGE);
#pragma unroll
            for (int kc = 0; kc < 4; kc++) {
                const uint32_t kb = kc * 32;
                uint32_t af[2][4];
                ldsm_x4(af[0], a_base + soff + kb);
                ldsm_x4(af[1], a_base + soff + 16 * RSA + kb);
#pragma unroll
                for (int np = 0; np < 2; np++) {
                    uint32_t bf[4];
                    ldsm_x4(bf, b_base + soff + np * (16 * RSB) + kb);
                    mma16816(acc[0][2 * np], af[0], bf);
                    mma16816(acc[1][2 * np], af[1], bf);
                    mma16816(acc[0][2 * np + 1], af[0], bf + 2);
                    mma16816(acc[1][2 * np + 1], af[1], bf + 2);
                }
            }
            __syncwarp();
            if (lane == 0) mbar_arrive(empty0 + slot * 8);
        }

        // ---- epilogue: red.add into zero-initialized out (4 k-partials) ----
        const int g = lane >> 2, q = lane & 3;
#pragma unroll
        for (int mt = 0; mt < 2; mt++) {
#pragma unroll
            for (int nt = 0; nt < 4; nt++) {
                int row = m0 + wm * 32 + mt * 16 + g;
                int col = wn * 32 + nt * 8 + 2 * q;
                float* p0 = out + (size_t)row * HID + col;
                float* p1 = out + (size_t)(row + 8) * HID + col;
                red_add(p0,     acc[mt][nt][0] * O_SCALE);
                red_add(p0 + 1, acc[mt][nt][1] * O_SCALE);
                red_add(p1,     acc[mt][nt][2] * O_SCALE);
                red_add(p1 + 1, acc[mt][nt][3] * O_SCALE);
            }
        }
    }
}

// ---------------------------------------------------------------------------
// launch
// ---------------------------------------------------------------------------
extern "C" void kernel_launch(void* const* d_in, const int* in_sizes, int n_in,
                              void* d_out, int out_size) {
    const float* x = nullptr;
    const float* G = nullptr;
    const float* W = nullptr;
    const float* b = nullptr;
    bool g_set = false;
    for (int i = 0; i < n_in; i++) {
        int sz = in_sizes[i];
        if (sz == NNODE * INDIM)       x = (const float*)d_in[i];
        else if (sz == NNODE * NNODE)  { if (!g_set) { G = (const float*)d_in[i]; g_set = true; } }
        else if (sz == HID * INDIM)    W = (const float*)d_in[i];
        else if (sz == HID)            b = (const float*)d_in[i];
    }
    if (!x && n_in > 0) x = (const float*)d_in[0];
    if (!G && n_in > 1) G = (const float*)d_in[1];
    if (!W && n_in > 3) W = (const float*)d_in[3];
    if (!b && n_in > 4) b = (const float*)d_in[4];

    cudaFuncSetAttribute(ht_kernel, cudaFuncAttributeMaxDynamicSharedMemorySize, H_SMEM);
    ht_kernel<<<NNODE / 32, 256, H_SMEM>>>(x, W, b, (float*)d_out);

    cudaFuncSetAttribute(gemm_kernel, cudaFuncAttributeMaxDynamicSharedMemorySize, SMEM_BYTES);
    gemm_kernel<<<dim3(NNODE / 64, 4), 512, SMEM_BYTES>>>(G, (float*)d_out);
}

// round 16
// speedup vs baseline: 1.0818x; 1.0818x over previous
#include <cuda_runtime.h>
#include <cuda_fp16.h>
#include <cstdint>

#define NNODE 8192
#define INDIM 256
#define HID   128

__device__ __half g_Ht16[HID * NNODE];

// ---------------------------------------------------------------------------
// helpers
// ---------------------------------------------------------------------------
__device__ __forceinline__ void mbar_init(uint32_t a, uint32_t n) {
    asm volatile("mbarrier.init.shared.b64 [%0], %1;" :: "r"(a), "r"(n) : "memory");
}
__device__ __forceinline__ void mbar_arrive(uint32_t a) {
    asm volatile("mbarrier.arrive.release.cta.shared::cta.b64 _, [%0];" :: "r"(a) : "memory");
}
__device__ __forceinline__ void mbar_wait(uint32_t a, uint32_t parity) {
    asm volatile(
        "{\n\t.reg .pred P;\n\t"
        "WL_%=:\n\t"
        "mbarrier.try_wait.parity.acquire.cta.shared::cta.b64 P, [%0], %1, 0x989680;\n\t"
        "@P bra.uni WD_%=;\n\t"
        "bra.uni WL_%=;\n\t"
        "WD_%=:\n\t}"
        :: "r"(a), "r"(parity) : "memory");
}
__device__ __forceinline__ void cp_async16(uint32_t smem_dst, const void* gmem_src) {
    asm volatile("cp.async.cg.shared.global [%0], [%1], 16;" :: "r"(smem_dst), "l"(gmem_src));
}
__device__ __forceinline__ void ldsm_x4(uint32_t* r, uint32_t addr) {
    asm volatile("ldmatrix.sync.aligned.m8n8.x4.shared.b16 {%0,%1,%2,%3}, [%4];"
        : "=r"(r[0]), "=r"(r[1]), "=r"(r[2]), "=r"(r[3]) : "r"(addr));
}
__device__ __forceinline__ void mma16816(float* d, const uint32_t* a, const uint32_t* bfr) {
    asm volatile(
        "mma.sync.aligned.m16n8k16.row.col.f32.f16.f16.f32 "
        "{%0,%1,%2,%3}, {%4,%5,%6,%7}, {%8,%9}, {%0,%1,%2,%3};"
        : "+f"(d[0]), "+f"(d[1]), "+f"(d[2]), "+f"(d[3])
        : "r"(a[0]), "r"(a[1]), "r"(a[2]), "r"(a[3]), "r"(bfr[0]), "r"(bfr[1]));
}
__device__ __forceinline__ void red_add(float* p, float v) {
    asm volatile("red.global.add.f32 [%0], %1;" :: "l"(p), "f"(v) : "memory");
}

// ---------------------------------------------------------------------------
// Kernel 1 (tensor-core): Ht16 = fp16( W @ x^T + b )   + zeroes `out`
//   (unchanged from round-13 winner)
// ---------------------------------------------------------------------------
static constexpr int H_RS    = 528;
static constexpr int H_SW    = 0;
static constexpr int H_SX    = 128 * H_RS;
static constexpr int H_SB    = H_SX + 32 * H_RS;
static constexpr int H_SMEM  = H_SB + 512;
static constexpr int H_TRS   = 80;
#define W_SCALE 32.0f
#define W_INV   (1.0f / 32.0f)

__global__ void __launch_bounds__(256, 2) ht_kernel(const float* __restrict__ x,
                                                    const float* __restrict__ W,
                                                    const float* __restrict__ b,
                                                    float* __restrict__ out) {
    extern __shared__ char hsm[];
    const uint32_t sm = (uint32_t)__cvta_generic_to_shared(hsm);
    const int tid = threadIdx.x;
    const int wid = tid >> 5, lane = tid & 31;
    const int j0  = blockIdx.x * 32;

    {
        float4* oz = reinterpret_cast<float4*>(out) + (size_t)blockIdx.x * 1024;
#pragma unroll
        for (int i = 0; i < 4; i++)
            oz[tid + i * 256] = make_float4(0.f, 0.f, 0.f, 0.f);
    }

    const float4* wg = reinterpret_cast<const float4*>(W);
#pragma unroll
    for (int i = 0; i < 32; i++) {
        int idx = tid + i * 256;
        int row = idx >> 6, c4 = idx & 63;
        float4 v = __ldg(wg + idx);
        __half2 h0 = __floats2half2_rn(v.x * W_SCALE, v.y * W_SCALE);
        __half2 h1 = __floats2half2_rn(v.z * W_SCALE, v.w * W_SCALE);
        asm volatile("st.shared.v2.b32 [%0], {%1,%2};" ::
            "r"(sm + H_SW + row * H_RS + c4 * 8),
            "r"(*(uint32_t*)&h0), "r"(*(uint32_t*)&h1) : "memory");
    }
    const float4* xg = reinterpret_cast<const float4*>(x + (size_t)j0 * INDIM);
#pragma unroll
    for (int i = 0; i < 8; i++) {
        int idx = tid + i * 256;
        int row = idx >> 6, c4 = idx & 63;
        float4 v = __ldg(xg + idx);
        __half2 h0 = __floats2half2_rn(v.x, v.y);
        __half2 h1 = __floats2half2_rn(v.z, v.w);
        asm volatile("st.shared.v2.b32 [%0], {%1,%2};" ::
            "r"(sm + H_SX + row * H_RS + c4 * 8),
            "r"(*(uint32_t*)&h0), "r"(*(uint32_t*)&h1) : "memory");
    }
    if (tid < 128)
        reinterpret_cast<float*>(hsm + H_SB)[tid] = b[tid];
    __syncthreads();

    const int wm = wid >> 1, wn = wid & 1;
    const int g = lane >> 2, q = lane & 3;
    const uint32_t a_lo = (uint32_t)((lane & 15) * H_RS + (lane >> 4) * 16);
    const uint32_t b_lo = (uint32_t)((lane & 7) * H_RS + ((lane >> 3) & 1) * 16
                                     + (lane >> 4) * (8 * H_RS));
    const uint32_t a_base = sm + H_SW + wm * (32 * H_RS) + a_lo;
    const uint32_t b_base = sm + H_SX + wn * (16 * H_RS) + b_lo;

    float acc[2][2][4];
#pragma unroll
    for (int mt = 0; mt < 2; mt++)
#pragma unroll
        for (int nt = 0; nt < 2; nt++)
#pragma unroll
            for (int i = 0; i < 4; i++) acc[mt][nt][i] = 0.f;

#pragma unroll
    for (int kc = 0; kc < 16; kc++) {
        const uint32_t kb = kc * 32;
        uint32_t af[2][4], bf[4];
        ldsm_x4(af[0], a_base + kb);
        ldsm_x4(af[1], a_base + 16 * H_RS + kb);
        ldsm_x4(bf, b_base + kb);
        mma16816(acc[0][0], af[0], bf);
        mma16816(acc[1][0], af[1], bf);
        mma16816(acc[0][1], af[0], bf + 2);
        mma16816(acc[1][1], af[1], bf + 2);
    }
    __syncthreads();

    const float* bs = reinterpret_cast<const float*>(hsm + H_SB);
#pragma unroll
    for (int mt = 0; mt < 2; mt++) {
        int c0 = wm * 32 + mt * 16 + g;
        float b0 = bs[c0], b1 = bs[c0 + 8];
#pragma unroll
        for (int nt = 0; nt < 2; nt++) {
            int j = wn * 16 + nt * 8 + 2 * q;
            __half2 h0 = __floats2half2_rn(fmaf(acc[mt][nt][0], W_INV, b0),
                                           fmaf(acc[mt][nt][1], W_INV, b0));
            __half2 h1 = __floats2half2_rn(fmaf(acc[mt][nt][2], W_INV, b1),
                                           fmaf(acc[mt][nt][3], W_INV, b1));
            asm volatile("st.shared.b32 [%0], %1;" ::
                "r"(sm + c0 * H_TRS + j * 2), "r"(*(uint32_t*)&h0) : "memory");
            asm volatile("st.shared.b32 [%0], %1;" ::
                "r"(sm + (c0 + 8) * H_TRS + j * 2), "r"(*(uint32_t*)&h1) : "memory");
        }
    }
    __syncthreads();

#pragma unroll
    for (int i = 0; i < 2; i++) {
        int idx = tid + i * 256;
        int row = idx >> 2, c16 = idx & 3;
        uint32_t r0, r1, r2, r3;
        asm volatile("ld.shared.v4.b32 {%0,%1,%2,%3}, [%4];"
            : "=r"(r0), "=r"(r1), "=r"(r2), "=r"(r3)
            : "r"(sm + row * H_TRS + c16 * 16));
        *reinterpret_cast<uint4*>(g_Ht16 + (size_t)row * NNODE + j0 + c16 * 8) =
            make_uint4(r0, r1, r2, r3);
    }
}

// ---------------------------------------------------------------------------
// Kernel 2: out += G @ H. Grid (64 mtiles, 4 kquarters) = 256 CTAs.
//   768 thr/CTA, 1 CTA/SM: warps 0-7 producers, 8-23 consumers (4M x 4N).
//   M=128, N=128, K=2048/CTA, KT=64, S=4. red.add epilogue.
// ---------------------------------------------------------------------------
static constexpr int S      = 4;
static constexpr int KT     = 64;
static constexpr int KQ     = NNODE / 4;       // 2048
static constexpr int NS     = KQ / KT;         // 32
static constexpr int RSA    = 144;
static constexpr int RSB    = 144;
static constexpr int A_SM   = 128 * RSA;       // 18432
static constexpr int B_SM   = 128 * RSB;       // 18432
static constexpr int STAGE  = A_SM + B_SM;     // 36864
static constexpr int TILE0  = 1024;
static constexpr int SMEM_BYTES = TILE0 + S * STAGE;  // 148480
#define A_SCALE 1024.0f
#define O_SCALE (1.0f / 1024.0f)

__global__ void __launch_bounds__(768, 1) gemm_kernel(const float* __restrict__ G,
                                                      float* __restrict__ out) {
    extern __shared__ char smem[];
    const uint32_t sb     = (uint32_t)__cvta_generic_to_shared(smem);
    const uint32_t full0  = sb;
    const uint32_t empty0 = sb + 64;
    const uint32_t tiles  = sb + TILE0;

    const int tid = threadIdx.x;
    const int wid = tid >> 5, lane = tid & 31;
    const int m0  = blockIdx.x * 128;
    const int k0  = blockIdx.y * KQ;

    if (tid == 0) {
#pragma unroll
        for (int s = 0; s < S; s++) {
            mbar_init(full0 + s * 8, 8);    // 8 producer warps
            mbar_init(empty0 + s * 8, 16);  // 16 consumer warps
        }
    }
    __syncthreads();

    if (wid < 8) {
        // ============ producers (256 threads) ============
        const int r0 = tid >> 4, c16 = tid & 15;
        const int br0 = tid >> 3, c8 = tid & 7;
        const float4* a_src = reinterpret_cast<const float4*>(
            G + (size_t)(m0 + r0) * NNODE + k0) + c16;
        const __half* b_src = g_Ht16 + (size_t)br0 * NNODE + k0 + c8 * 8;
        const uint32_t a_dst = (uint32_t)(r0 * RSA + c16 * 8);
        const uint32_t b_dst = (uint32_t)(A_SM + br0 * RSB + c8 * 16);

        // depth-1 prefetch buffer: 8 chunks (rows r0+16i)
        float4 buf[8];
#pragma unroll
        for (int i = 0; i < 8; i++)
            buf[i] = __ldcs(a_src + (size_t)i * 16 * NNODE / 4);

        int aslot = 0;
        for (int s = 0; s < NS; s++) {
            const int slot = s & 3, lap = s >> 2;
            if (lap > 0) mbar_wait(empty0 + slot * 8, (lap - 1) & 1);
            const uint32_t st = tiles + slot * STAGE;
            // B cp.async: 4 chunks
#pragma unroll
            for (int i = 0; i < 4; i++)
                cp_async16(st + b_dst + i * (32 * RSB), b_src + (size_t)i * 32 * NNODE + s * KT);
            asm volatile("cp.async.commit_group;" ::: "memory");
            // A cvt + STS: 8 chunks
#pragma unroll
            for (int i = 0; i < 8; i++) {
                float4 v = buf[i];
                __half2 h0 = __floats2half2_rn(v.x * A_SCALE, v.y * A_SCALE);
                __half2 h1 = __floats2half2_rn(v.z * A_SCALE, v.w * A_SCALE);
                asm volatile("st.shared.v2.b32 [%0], {%1,%2};" ::
                    "r"(st + a_dst + i * (16 * RSA)),
                    "r"(*(uint32_t*)&h0), "r"(*(uint32_t*)&h1) : "memory");
            }
            // prefetch A for stage s+1
            if (s + 1 < NS) {
#pragma unroll
                for (int i = 0; i < 8; i++)
                    buf[i] = __ldcs(a_src + (size_t)i * 16 * NNODE / 4 + (s + 1) * (KT / 4));
            }
            // lagged full-arrival for stage s-2 (elected)
            if (s >= 2) {
                asm volatile("cp.async.wait_group 2;" ::: "memory");
                __syncwarp();
                if (lane == 0) mbar_arrive(full0 + aslot * 8);
                if (++aslot == S) aslot = 0;
            }
        }
        asm volatile("cp.async.wait_group 0;" ::: "memory");
        __syncwarp();
        if (lane == 0) {
            mbar_arrive(full0 + aslot * 8);
            int a2 = aslot + 1; if (a2 == S) a2 = 0;
            mbar_arrive(full0 + a2 * 8);
        }
    } else {
        // ============ consumers (16 warps, grid 4M x 4N, warp tile 32x32) ============
        const int cw = wid - 8;
        const int wm = cw >> 2, wn = cw & 3;
        const uint32_t a_lo = (uint32_t)((lane & 15) * RSA + (lane >> 4) * 16);
        const uint32_t b_lo = (uint32_t)((lane & 7) * RSB + ((lane >> 3) & 1) * 16
                                         + (lane >> 4) * (8 * RSB));
        const uint32_t a_base = tiles + wm * (32 * RSA) + a_lo;
        const uint32_t b_base = tiles + A_SM + wn * (32 * RSB) + b_lo;

        float acc[2][4][4];
#pragma unroll
        for (int mt = 0; mt < 2; mt++)
#pragma unroll
            for (int nt = 0; nt < 4; nt++)
#pragma unroll
                for (int i = 0; i < 4; i++) acc[mt][nt][i] = 0.f;

        for (int s = 0; s < NS; s++) {
            const int slot = s & 3;
            mbar_wait(full0 + slot * 8, (s >> 2) & 1);
            const uint32_t soff = (uint32_t)(slot * STAGE);
#pragma unroll
            for (int kc = 0; kc < 4; kc++) {
                const uint32_t kb = kc * 32;
                uint32_t af[2][4];
                ldsm_x4(af[0], a_base + soff + kb);
                ldsm_x4(af[1], a_base + soff + 16 * RSA + kb);
#pragma unroll
                for (int np = 0; np < 2; np++) {
                    uint32_t bf[4];
                    ldsm_x4(bf, b_base + soff + np * (16 * RSB) + kb);
                    mma16816(acc[0][2 * np], af[0], bf);
                    mma16816(acc[1][2 * np], af[1], bf);
                    mma16816(acc[0][2 * np + 1], af[0], bf + 2);
                    mma16816(acc[1][2 * np + 1], af[1], bf + 2);
                }
            }
            __syncwarp();
            if (lane == 0) mbar_arrive(empty0 + slot * 8);
        }

        // ---- epilogue: red.add into zero-initialized out (4 k-partials) ----
        const int g = lane >> 2, q = lane & 3;
#pragma unroll
        for (int mt = 0; mt < 2; mt++) {
#pragma unroll
            for (int nt = 0; nt < 4; nt++) {
                int row = m0 + wm * 32 + mt * 16 + g;
                int col = wn * 32 + nt * 8 + 2 * q;
                float* p0 = out + (size_t)row * HID + col;
                float* p1 = out + (size_t)(row + 8) * HID + col;
                red_add(p0,     acc[mt][nt][0] * O_SCALE);
                red_add(p0 + 1, acc[mt][nt][1] * O_SCALE);
                red_add(p1,     acc[mt][nt][2] * O_SCALE);
                red_add(p1 + 1, acc[mt][nt][3] * O_SCALE);
            }
        }
    }
}

// ---------------------------------------------------------------------------
// launch
// ---------------------------------------------------------------------------
extern "C" void kernel_launch(void* const* d_in, const int* in_sizes, int n_in,
                              void* d_out, int out_size) {
    const float* x = nullptr;
    const float* G = nullptr;
    const float* W = nullptr;
    const float* b = nullptr;
    bool g_set = false;
    for (int i = 0; i < n_in; i++) {
        int sz = in_sizes[i];
        if (sz == NNODE * INDIM)       x = (const float*)d_in[i];
        else if (sz == NNODE * NNODE)  { if (!g_set) { G = (const float*)d_in[i]; g_set = true; } }
        else if (sz == HID * INDIM)    W = (const float*)d_in[i];
        else if (sz == HID)            b = (const float*)d_in[i];
    }
    if (!x && n_in > 0) x = (const float*)d_in[0];
    if (!G && n_in > 1) G = (const float*)d_in[1];
    if (!W && n_in > 3) W = (const float*)d_in[3];
    if (!b && n_in > 4) b = (const float*)d_in[4];

    cudaFuncSetAttribute(ht_kernel, cudaFuncAttributeMaxDynamicSharedMemorySize, H_SMEM);
    ht_kernel<<<NNODE / 32, 256, H_SMEM>>>(x, W, b, (float*)d_out);

    cudaFuncSetAttribute(gemm_kernel, cudaFuncAttributeMaxDynamicSharedMemorySize, SMEM_BYTES);
    gemm_kernel<<<dim3(NNODE / 128, 4), 768, SMEM_BYTES>>>(G, (float*)d_out);
}